// round 3
// baseline (speedup 1.0000x reference)
#include <cuda_runtime.h>
#include <cstdint>

#define EPSF 1e-5f
#define SCALE 0.17677669529663687f

// scratch
__device__ float g_qn[2*384*128];
__device__ float g_kn[2*384*128];
__device__ float g_vn[2*384*128];
__device__ float g_ao[2*384*128];
__device__ float g_Pc[2*384*64];
__device__ float g_Pd[2*384*64];
__device__ float g_WQT[64*128];
__device__ float g_WKT[64*128];

// ---- transpose weq/wek: WQT[c][o] = weq[o][c] ----
__global__ void k_prep(const float* __restrict__ weq, const float* __restrict__ wek){
    int idx = blockIdx.x*256 + threadIdx.x;
    if (idx < 8192){ int c=idx>>7, o=idx&127; g_WQT[idx]=weq[o*64+c]; }
    else if (idx < 16384){ int t=idx-8192; int c=t>>7, o=t&127; g_WKT[t]=wek[o*64+c]; }
}

// ---- qn/kn/vn = x @ W^T, one CTA per row ----
__global__ void __launch_bounds__(128) k_qkv(const float* __restrict__ x,
    const float* __restrict__ wnq, const float* __restrict__ wnk, const float* __restrict__ wnv){
    __shared__ float sx[128];
    int r = blockIdx.x, t = threadIdx.x;
    sx[t] = x[r*128+t];
    __syncthreads();
    float aq=0.f, ak=0.f, av=0.f;
    int base = t*128;
#pragma unroll 8
    for (int c=0;c<128;++c){
        float xv = sx[c];
        aq += __ldg(&wnq[base+c])*xv;
        ak += __ldg(&wnk[base+c])*xv;
        av += __ldg(&wnv[base+c])*xv;
    }
    g_qn[r*128+t]=aq; g_kn[r*128+t]=ak; g_vn[r*128+t]=av;
}

// ---- attention: one CTA per (b,i), 256 threads ----
// smem floats: WQT 8192 | WKT 8192 | WV 8192 | Q 128 | S 3072 | arow 512 | AW 4096 | OV 1024 | TOT 512 | OVT 128
#define ATTN_SMEM (34048*4)
__global__ void __launch_bounds__(256) k_attn(const float* __restrict__ adj, const float* __restrict__ wev){
    extern __shared__ float sm[];
    float* sWQT=sm;         float* sWKT=sm+8192;  float* sWV=sm+16384;
    float* sQ=sm+24576;     float* sS=sm+24704;   float* sAdj=sm+27776;
    float* sAW=sm+28288;    float* sOV=sm+32384;  float* sTOT=sm+33408; float* sOVT=sm+33920;
    int bi=blockIdx.x, b=bi/384;
    int tid=threadIdx.x, w=tid>>5, l=tid&31, h2l=l>>2;
    for (int idx=tid; idx<8192; idx+=256){ sWQT[idx]=g_WQT[idx]; sWKT[idx]=g_WKT[idx]; sWV[idx]=wev[idx]; }
    if (tid<128) sQ[tid]=g_qn[bi*128+tid];
    __syncthreads();
    const float* adj_i = adj + (size_t)bi*24576;   // [j][64]
    float4 qreg = ((const float4*)sQ)[l];
    float* arow = sAdj + w*64;
    // phase 1: scores
    for (int jj=0; jj<48; ++jj){
        int j = w*48 + jj;
        ((float2*)arow)[l] = ((const float2*)(adj_i + j*64))[l];
        float4 kr = ((const float4*)(g_kn + (size_t)(b*384+j)*128))[l];
        __syncwarp();
        float e0=0,e1=0,e2=0,e3=0,f0=0,f1=0,f2=0,f3=0;
#pragma unroll 8
        for (int c=0;c<64;++c){
            float a = arow[c];
            float4 wq = ((const float4*)(sWQT + c*128))[l];
            float4 wk = ((const float4*)(sWKT + c*128))[l];
            e0+=wq.x*a; e1+=wq.y*a; e2+=wq.z*a; e3+=wq.w*a;
            f0+=wk.x*a; f1+=wk.y*a; f2+=wk.z*a; f3+=wk.w*a;
        }
        float s = (qreg.x+e0)*(kr.x+f0)+(qreg.y+e1)*(kr.y+f1)+(qreg.z+e2)*(kr.z+f2)+(qreg.w+e3)*(kr.w+f3);
        s += __shfl_xor_sync(0xffffffffu,s,1);
        s += __shfl_xor_sync(0xffffffffu,s,2);
        if ((l&3)==0) sS[h2l*384 + j] = s*SCALE;
        __syncwarp();
    }
    __syncthreads();
    // phase 2: softmax, warp w = head w
    {
        float vals[12]; float m=-1e30f;
#pragma unroll
        for (int q=0;q<12;++q){ vals[q]=sS[w*384+q*32+l]; m=fmaxf(m,vals[q]); }
#pragma unroll
        for (int off=16;off;off>>=1) m=fmaxf(m,__shfl_xor_sync(0xffffffffu,m,off));
        float Z=0.f;
#pragma unroll
        for (int q=0;q<12;++q){ vals[q]=__expf(vals[q]-m); Z+=vals[q]; }
#pragma unroll
        for (int off=16;off;off>>=1) Z+=__shfl_xor_sync(0xffffffffu,Z,off);
        float inv=1.0f/Z;
#pragma unroll
        for (int q=0;q<12;++q) sS[w*384+q*32+l]=vals[q]*inv;
    }
    __syncthreads();
    // phase 3: accumulate attn-weighted adj + vn
    {
        float aw0[8], aw1[8]; float4 ov = make_float4(0,0,0,0);
#pragma unroll
        for (int h=0;h<8;++h){ aw0[h]=0.f; aw1[h]=0.f; }
        for (int jj=0; jj<48; ++jj){
            int j=w*48+jj;
            float ah[8];
#pragma unroll
            for (int h=0;h<8;++h) ah[h]=sS[h*384+j];
            float2 av = ((const float2*)(adj_i + j*64))[l];
#pragma unroll
            for (int h=0;h<8;++h){ aw0[h]+=ah[h]*av.x; aw1[h]+=ah[h]*av.y; }
            float4 vv = ((const float4*)(g_vn + (size_t)(b*384+j)*128))[l];
            float a = ah[h2l];
            ov.x+=a*vv.x; ov.y+=a*vv.y; ov.z+=a*vv.z; ov.w+=a*vv.w;
        }
#pragma unroll
        for (int h=0;h<8;++h){ sAW[(w*8+h)*64 + 2*l]=aw0[h]; sAW[(w*8+h)*64 + 2*l+1]=aw1[h]; }
        ((float4*)(sOV + w*128))[l]=ov;
    }
    __syncthreads();
    for (int idx=tid; idx<512; idx+=256){
        float s=0.f;
#pragma unroll
        for (int w2=0;w2<8;++w2) s+=sAW[w2*512+idx];
        sTOT[idx]=s;
    }
    if (tid<128){
        float s=0.f;
#pragma unroll
        for (int w2=0;w2<8;++w2) s+=sOV[w2*128+tid];
        sOVT[tid]=s;
    }
    __syncthreads();
    if (tid<128){
        int h=tid>>4;
        float acc=sOVT[tid];
#pragma unroll 8
        for (int c=0;c<64;++c){
            int cc=(c+tid)&63;
            acc += sWV[tid*64+cc]*sTOT[h*64+cc];
        }
        g_ao[bi*128 + (tid&15)*8 + h] = acc;   // torch interleave [B,N,d,H]
    }
}

// ---- node post: nfc1+LN1+FFN+LN2, plus Pc/Pd precompute ----
__global__ void __launch_bounds__(128) k_node(const float* __restrict__ x,
    const float* __restrict__ nfc1_w, const float* __restrict__ nfc1_b,
    const float* __restrict__ ln1_g, const float* __restrict__ ln1_b,
    const float* __restrict__ nfc2_w, const float* __restrict__ nfc2_b,
    const float* __restrict__ nfc3_w, const float* __restrict__ nfc3_b,
    const float* __restrict__ ln2_g, const float* __restrict__ ln2_b,
    const float* __restrict__ efc1_w, float* __restrict__ out_x){
    __shared__ float sx[128], sao[128], sx1[128], sh[256], sx2[128], sred[8];
    int r=blockIdx.x, t=threadIdx.x;
    sx[t]=x[r*128+t]; sao[t]=g_ao[r*128+t];
    __syncthreads();
    // nfc1
    float acc = __ldg(&nfc1_b[t]);
#pragma unroll 8
    for (int c=0;c<128;++c) acc += __ldg(&nfc1_w[t*128+c])*sao[c];
    float val = sx[t] + acc;
    // LN1
    {
        float s=val, s2=val*val;
#pragma unroll
        for (int off=16;off;off>>=1){ s+=__shfl_xor_sync(0xffffffffu,s,off); s2+=__shfl_xor_sync(0xffffffffu,s2,off); }
        if ((t&31)==0){ sred[(t>>5)*2]=s; sred[(t>>5)*2+1]=s2; }
        __syncthreads();
        float S=sred[0]+sred[2]+sred[4]+sred[6], S2=sred[1]+sred[3]+sred[5]+sred[7];
        float m=S*(1.f/128.f), var=S2*(1.f/128.f)-m*m, rs=rsqrtf(var+EPSF);
        sx1[t]=(val-m)*rs*__ldg(&ln1_g[t])+__ldg(&ln1_b[t]);
        __syncthreads();
    }
    // nfc2 + relu
    float a0=__ldg(&nfc2_b[t]), a1=__ldg(&nfc2_b[t+128]);
#pragma unroll 8
    for (int c=0;c<128;++c){
        float xv=sx1[c];
        a0 += __ldg(&nfc2_w[t*128+c])*xv;
        a1 += __ldg(&nfc2_w[(t+128)*128+c])*xv;
    }
    sh[t]=fmaxf(a0,0.f); sh[t+128]=fmaxf(a1,0.f);
    __syncthreads();
    // nfc3
    float acc3=__ldg(&nfc3_b[t]);
#pragma unroll 8
    for (int c=0;c<256;++c) acc3 += __ldg(&nfc3_w[t*256+c])*sh[c];
    float v2 = sx1[t] + acc3;
    // LN2
    {
        float s=v2, s2=v2*v2;
#pragma unroll
        for (int off=16;off;off>>=1){ s+=__shfl_xor_sync(0xffffffffu,s,off); s2+=__shfl_xor_sync(0xffffffffu,s2,off); }
        if ((t&31)==0){ sred[(t>>5)*2]=s; sred[(t>>5)*2+1]=s2; }
        __syncthreads();
        float S=sred[0]+sred[2]+sred[4]+sred[6], S2=sred[1]+sred[3]+sred[5]+sred[7];
        float m=S*(1.f/128.f), var=S2*(1.f/128.f)-m*m, rs=rsqrtf(var+EPSF);
        float x2v=(v2-m)*rs*__ldg(&ln2_g[t])+__ldg(&ln2_b[t]);
        out_x[r*128+t]=x2v; sx2[t]=x2v;
        __syncthreads();
    }
    // Pc/Pd
    if (t<64){
        float pc=0.f, pd=0.f;
#pragma unroll 8
        for (int c=0;c<128;++c){
            float xv=sx2[c];
            pc += __ldg(&efc1_w[t*384+128+c])*xv;
            pd += __ldg(&efc1_w[t*384+256+c])*xv;
        }
        g_Pc[r*64+t]=pc; g_Pd[r*64+t]=pd;
    }
}

// ---- edge MLP: CTA = (b,i, 64-j tile), 256 threads, warp = 8 pairs ----
// floats: Wa 4096 | Wb 4096 | W2 4096 | W3 8192 | W4 8192 | AI 4096 | AJ 4096 | Pc 4096 | Pd 64 | B 576 | Wk 2048
#define EDGE_SMEM (43648*4)
__global__ void __launch_bounds__(256) k_edge(const float* __restrict__ adj,
    const float* __restrict__ efc1_w, const float* __restrict__ efc1_b,
    const float* __restrict__ efc2_w, const float* __restrict__ efc2_b,
    const float* __restrict__ eg1, const float* __restrict__ eb1,
    const float* __restrict__ efc3_w, const float* __restrict__ efc3_b,
    const float* __restrict__ efc4_w, const float* __restrict__ efc4_b,
    const float* __restrict__ eg2, const float* __restrict__ eb2,
    float* __restrict__ out_adj){
    extern __shared__ float sm[];
    float* sWa=sm;        float* sWb=sm+4096;   float* sW2=sm+8192;
    float* sW3=sm+12288;  float* sW4=sm+20480;
    float* sAI=sm+28672;  float* sAJ=sm+32768;  float* sPc=sm+36864;
    float* sPd=sm+40960;  float* sB=sm+41024;   float* sWk=sm+41600;
    int tid=threadIdx.x;
    int bi=blockIdx.x/6, jt=blockIdx.x%6;
    int b=bi/384, i=bi%384, j0=jt*64;
    for (int idx=tid; idx<4096; idx+=256){
        int o=idx>>6, c=idx&63;
        sWa[idx]=efc1_w[o*384+c];
        sWb[idx]=efc1_w[o*384+64+c];
        sW2[idx]=efc2_w[idx];
    }
    for (int idx=tid; idx<8192; idx+=256){ sW3[idx]=efc3_w[idx]; sW4[idx]=efc4_w[idx]; }
    const float* adjb = adj + (size_t)b*9437184;
    for (int idx=tid; idx<4096; idx+=256){
        int jj=idx>>6, c=idx&63;
        sAI[idx]=adjb[((size_t)i*384 + j0+jj)*64 + c];
        sAJ[idx]=adjb[((size_t)(j0+jj)*384 + i)*64 + c];
        sPc[idx]=g_Pc[(b*384 + j0+jj)*64 + c];
    }
    if (tid<64){
        sPd[tid]=g_Pd[bi*64+tid];
        sB[tid]=efc1_b[tid]; sB[64+tid]=efc2_b[tid]; sB[256+tid]=efc4_b[tid];
        sB[320+tid]=eg1[tid]; sB[384+tid]=eb1[tid]; sB[448+tid]=eg2[tid]; sB[512+tid]=eb2[tid];
    }
    if (tid<128) sB[128+tid]=efc3_b[tid];
    __syncthreads();
    int w=tid>>5, l=tid&31;
    float* swk = sWk + w*256;       // h1:0-63 | h3:64-191 | adj1:192-255
    const float2* Wa2=(const float2*)sWa; const float2* Wb2=(const float2*)sWb;
    const float2* W22=(const float2*)sW2; const float2* W32=(const float2*)sW3;
    const float2* W42=(const float2*)sW4;
    int o0=l, o1=l+32;
    for (int p=0;p<8;++p){
        int jj=w*8+p;
        const float2* AI2=(const float2*)(sAI+jj*64);
        const float2* AJ2=(const float2*)(sAJ+jj*64);
        // efc1 (Wa*adj_ij + Wb*adj_ji + Pc + Pd + b1), relu
        float acc0=sB[o0]+sPc[jj*64+o0]+sPd[o0];
        float acc1=sB[o1]+sPc[jj*64+o1]+sPd[o1];
#pragma unroll
        for (int c=0;c<32;++c){
            int cc=(c+l)&31;
            float2 a=AI2[cc], r=AJ2[cc];
            float2 w0=Wa2[o0*32+cc], w1=Wa2[o1*32+cc];
            float2 u0=Wb2[o0*32+cc], u1=Wb2[o1*32+cc];
            acc0 += w0.x*a.x+w0.y*a.y + u0.x*r.x+u0.y*r.y;
            acc1 += w1.x*a.x+w1.y*a.y + u1.x*r.x+u1.y*r.y;
        }
        swk[o0]=fmaxf(acc0,0.f); swk[o1]=fmaxf(acc1,0.f);
        __syncwarp();
        // efc2
        const float2* H12=(const float2*)swk;
        float r0=sB[64+o0], r1=sB[64+o1];
#pragma unroll
        for (int c=0;c<32;++c){
            int cc=(c+l)&31;
            float2 h=H12[cc];
            float2 w0=W22[o0*32+cc], w1=W22[o1*32+cc];
            r0 += w0.x*h.x+w0.y*h.y;
            r1 += w1.x*h.x+w1.y*h.y;
        }
        float v0=sAI[jj*64+o0]+r0, v1=sAI[jj*64+o1]+r1;
        // LN1 (64)
        float S=v0+v1, S2=v0*v0+v1*v1;
#pragma unroll
        for (int off=16;off;off>>=1){ S+=__shfl_xor_sync(0xffffffffu,S,off); S2+=__shfl_xor_sync(0xffffffffu,S2,off); }
        float m=S*(1.f/64.f), var=S2*(1.f/64.f)-m*m, rs=rsqrtf(var+EPSF);
        float y0=(v0-m)*rs*sB[320+o0]+sB[384+o0];
        float y1=(v1-m)*rs*sB[320+o1]+sB[384+o1];
        swk[192+o0]=y0; swk[192+o1]=y1;
        __syncwarp();
        // efc3 (64->128), relu
        const float2* A12=(const float2*)(swk+192);
        float t0=sB[128+l], t1=sB[160+l], t2=sB[192+l], t3=sB[224+l];
#pragma unroll
        for (int c=0;c<32;++c){
            int cc=(c+l)&31;
            float2 hv=A12[cc];
            float2 w0=W32[l*32+cc], w1=W32[(l+32)*32+cc], w2=W32[(l+64)*32+cc], w3=W32[(l+96)*32+cc];
            t0+=w0.x*hv.x+w0.y*hv.y; t1+=w1.x*hv.x+w1.y*hv.y;
            t2+=w2.x*hv.x+w2.y*hv.y; t3+=w3.x*hv.x+w3.y*hv.y;
        }
        swk[64+l]=fmaxf(t0,0.f); swk[96+l]=fmaxf(t1,0.f); swk[128+l]=fmaxf(t2,0.f); swk[160+l]=fmaxf(t3,0.f);
        __syncwarp();
        // efc4 (128->64)
        const float2* H32=(const float2*)(swk+64);
        float q0=sB[256+o0], q1=sB[256+o1];
#pragma unroll
        for (int c=0;c<64;++c){
            int cc=(c+l)&63;
            float2 hv=H32[cc];
            float2 w0=W42[o0*64+cc], w1=W42[o1*64+cc];
            q0+=w0.x*hv.x+w0.y*hv.y;
            q1+=w1.x*hv.x+w1.y*hv.y;
        }
        float z0=y0+q0, z1=y1+q1;
        // LN2 (64)
        S=z0+z1; S2=z0*z0+z1*z1;
#pragma unroll
        for (int off=16;off;off>>=1){ S+=__shfl_xor_sync(0xffffffffu,S,off); S2+=__shfl_xor_sync(0xffffffffu,S2,off); }
        m=S*(1.f/64.f); var=S2*(1.f/64.f)-m*m; rs=rsqrtf(var+EPSF);
        size_t base = ((size_t)bi*384 + j0+jj)*64;
        out_adj[base+o0]=(z0-m)*rs*sB[448+o0]+sB[512+o0];
        out_adj[base+o1]=(z1-m)*rs*sB[448+o1]+sB[512+o1];
        __syncwarp();
    }
}

extern "C" void kernel_launch(void* const* d_in, const int* in_sizes, int n_in,
                              void* d_out, int out_size){
    const float* x       = (const float*)d_in[0];
    const float* adj     = (const float*)d_in[1];
    const float* wnq     = (const float*)d_in[2];
    const float* wnk     = (const float*)d_in[3];
    const float* wnv     = (const float*)d_in[4];
    const float* weq     = (const float*)d_in[5];
    const float* wek     = (const float*)d_in[6];
    const float* wev     = (const float*)d_in[7];
    const float* nfc1_w  = (const float*)d_in[8];
    const float* nfc1_b  = (const float*)d_in[9];
    const float* ln1_g   = (const float*)d_in[10];
    const float* ln1_b   = (const float*)d_in[11];
    const float* nfc2_w  = (const float*)d_in[12];
    const float* nfc2_b  = (const float*)d_in[13];
    const float* nfc3_w  = (const float*)d_in[14];
    const float* nfc3_b  = (const float*)d_in[15];
    const float* ln2_g   = (const float*)d_in[16];
    const float* ln2_b   = (const float*)d_in[17];
    const float* efc1_w  = (const float*)d_in[18];
    const float* efc1_b  = (const float*)d_in[19];
    const float* efc2_w  = (const float*)d_in[20];
    const float* efc2_b  = (const float*)d_in[21];
    const float* eln1_g  = (const float*)d_in[22];
    const float* eln1_b  = (const float*)d_in[23];
    const float* efc3_w  = (const float*)d_in[24];
    const float* efc3_b  = (const float*)d_in[25];
    const float* efc4_w  = (const float*)d_in[26];
    const float* efc4_b  = (const float*)d_in[27];
    const float* eln2_g  = (const float*)d_in[28];
    const float* eln2_b  = (const float*)d_in[29];
    float* out_x   = (float*)d_out;
    float* out_adj = out_x + 2*384*128;

    cudaFuncSetAttribute(k_attn, cudaFuncAttributeMaxDynamicSharedMemorySize, ATTN_SMEM);
    cudaFuncSetAttribute(k_edge, cudaFuncAttributeMaxDynamicSharedMemorySize, EDGE_SMEM);

    k_prep<<<64,256>>>(weq, wek);
    k_qkv<<<768,128>>>(x, wnq, wnk, wnv);
    k_attn<<<768,256,ATTN_SMEM>>>(adj, wev);
    k_node<<<768,128>>>(x, nfc1_w, nfc1_b, ln1_g, ln1_b, nfc2_w, nfc2_b,
                        nfc3_w, nfc3_b, ln2_g, ln2_b, efc1_w, out_x);
    k_edge<<<4608,256,EDGE_SMEM>>>(adj, efc1_w, efc1_b, efc2_w, efc2_b,
                                   eln1_g, eln1_b, efc3_w, efc3_b,
                                   efc4_w, efc4_b, eln2_g, eln2_b, out_adj);
}

// round 5
// speedup vs baseline: 4.2623x; 4.2623x over previous
#include <cuda_runtime.h>
#include <cstdint>

#define EPSF 1e-5f
#define SCALE 0.17677669529663687f

// scratch
__device__ float g_qn[2*384*128];
__device__ float g_kn[2*384*128];
__device__ float g_vn[2*384*128];
__device__ float g_ao[2*384*128];
__device__ float g_Pc[2*384*64];
__device__ float g_Pd[2*384*64];

// ============ k_qkv: 8 rows/CTA, smem-staged weights, 4-row blocking ============
#define QKV_SMEM (51744*4)
__global__ void __launch_bounds__(256) k_qkv(const float* __restrict__ x,
    const float* __restrict__ wnq, const float* __restrict__ wnk, const float* __restrict__ wnv){
    extern __shared__ float sm[];
    float* sWq = sm;             // 128*132
    float* sWk = sm + 16896;
    float* sWv = sm + 33792;
    float* sX  = sm + 50688;     // 8*132
    int tid = threadIdx.x;
    for (int idx=tid; idx<4096; idx+=256){
        int o = idx>>5, c4 = idx&31;
        *(float4*)(sWq + o*132 + c4*4) = *(const float4*)(wnq + o*128 + c4*4);
        *(float4*)(sWk + o*132 + c4*4) = *(const float4*)(wnk + o*128 + c4*4);
        *(float4*)(sWv + o*132 + c4*4) = *(const float4*)(wnv + o*128 + c4*4);
    }
    int r0 = blockIdx.x*8;
    { int r = tid>>5, c4 = tid&31;
      *(float4*)(sX + r*132 + c4*4) = *(const float4*)(x + (size_t)(r0+r)*128 + c4*4); }
    __syncthreads();
    int o = tid&127, g = tid>>7;
    float aq[4]={0,0,0,0}, ak[4]={0,0,0,0}, av[4]={0,0,0,0};
#pragma unroll 4
    for (int c4=0;c4<32;++c4){
        float4 wq = *(const float4*)(sWq + o*132 + c4*4);
        float4 wk = *(const float4*)(sWk + o*132 + c4*4);
        float4 wv = *(const float4*)(sWv + o*132 + c4*4);
#pragma unroll
        for (int rr=0;rr<4;++rr){
            float4 a = *(const float4*)(sX + (g*4+rr)*132 + c4*4);
            aq[rr] += wq.x*a.x+wq.y*a.y+wq.z*a.z+wq.w*a.w;
            ak[rr] += wk.x*a.x+wk.y*a.y+wk.z*a.z+wk.w*a.w;
            av[rr] += wv.x*a.x+wv.y*a.y+wv.z*a.z+wv.w*a.w;
        }
    }
#pragma unroll
    for (int rr=0;rr<4;++rr){
        int r = r0 + g*4 + rr;
        g_qn[r*128+o]=aq[rr]; g_kn[r*128+o]=ak[rr]; g_vn[r*128+o]=av[rr];
    }
}

// ============ k_attn: one CTA per (b,i) ============
// floats: sW 17408 @0 | sA 2176 @17408 | sS 3072 @19584 | sQ 128 @22656  => 22784
// phase3 overlay on sW: sWV 8192 @0 | sAW 4096 @8192 | sOV 1024 @12288 | sTOT 512 @13312 | sOVT 128 @13824
#define ATTN_SMEM (22784*4)
__global__ void __launch_bounds__(256) k_attn(const float* __restrict__ adj,
    const float* __restrict__ weq, const float* __restrict__ wek, const float* __restrict__ wev){
    extern __shared__ float sm[];
    float* sW = sm;
    float* sA = sm + 17408;
    float* sS = sm + 19584;
    float* sQ = sm + 22656;
    int bi = blockIdx.x, b = bi/384;
    int tid = threadIdx.x;
    int to = tid&31, tp = tid>>5;      // tp = warp id
    // load W = [weq ; wek] rows, stride 68
    for (int idx=tid; idx<4096; idx+=256){
        int o = idx>>4, c4 = idx&15;
        float4 v = (o<128) ? *(const float4*)(weq + o*64 + c4*4)
                           : *(const float4*)(wek + (o-128)*64 + c4*4);
        *(float4*)(sW + o*68 + c4*4) = v;
    }
    if (tid<128) sQ[tid] = g_qn[(size_t)bi*128 + tid];
    const float* adj_i = adj + (size_t)bi*24576;
    __syncthreads();

    // ---- phase 1: eq/ek GEMM + scores ----
    for (int jt=0; jt<12; ++jt){
        int j0 = jt*32;
        for (int idx=tid; idx<512; idx+=256){
            int p = idx>>4, c4 = idx&15;
            *(float4*)(sA + p*68 + c4*4) = *(const float4*)(adj_i + (size_t)(j0+p)*64 + c4*4);
        }
        __syncthreads();
        float acc[4][8];
#pragma unroll
        for (int p=0;p<4;++p)
#pragma unroll
            for (int o=0;o<8;++o) acc[p][o]=0.f;
#pragma unroll 2
        for (int c4=0;c4<16;++c4){
            float4 a[4], w[8];
#pragma unroll
            for (int k=0;k<4;++k) a[k] = *(const float4*)(sA + (tp*4+k)*68 + c4*4);
#pragma unroll
            for (int k=0;k<8;++k) w[k] = *(const float4*)(sW + (k*32+to)*68 + c4*4);
#pragma unroll
            for (int p=0;p<4;++p)
#pragma unroll
                for (int o=0;o<8;++o)
                    acc[p][o] += a[p].x*w[o].x + a[p].y*w[o].y + a[p].z*w[o].z + a[p].w*w[o].w;
        }
#pragma unroll
        for (int pp=0;pp<4;++pp){
            int j = j0 + tp*4 + pp;
            const float* kr = g_kn + (size_t)(b*384+j)*128;
#pragma unroll
            for (int m=0;m<4;++m){
                int d = m*32 + to;
                float eq = sQ[d] + acc[pp][m];
                float ek = __ldg(&kr[d]) + acc[pp][m+4];
                float pr = eq*ek;
                pr += __shfl_xor_sync(0xffffffffu, pr, 1);
                pr += __shfl_xor_sync(0xffffffffu, pr, 2);
                pr += __shfl_xor_sync(0xffffffffu, pr, 4);
                pr += __shfl_xor_sync(0xffffffffu, pr, 8);
                if ((to&15)==0) sS[(2*m + (to>>4))*384 + j] = pr*SCALE;
            }
        }
        __syncthreads();
    }

    // load sWV (overwrites sW region, dead now)
    float* sWV = sm;
    float* sAW = sm + 8192;
    float* sOV = sm + 12288;
    float* sTOT= sm + 13312;
    float* sOVT= sm + 13824;
    for (int idx=tid; idx<8192; idx+=256) sWV[idx]=wev[idx];
    __syncthreads();

    // ---- phase 2: softmax, warp = head ----
    {
        int w = tp, l = to;
        float vals[12]; float m=-1e30f;
#pragma unroll
        for (int q=0;q<12;++q){ vals[q]=sS[w*384+q*32+l]; m=fmaxf(m,vals[q]); }
#pragma unroll
        for (int off=16;off;off>>=1) m=fmaxf(m,__shfl_xor_sync(0xffffffffu,m,off));
        float Z=0.f;
#pragma unroll
        for (int q=0;q<12;++q){ vals[q]=__expf(vals[q]-m); Z+=vals[q]; }
#pragma unroll
        for (int off=16;off;off>>=1) Z+=__shfl_xor_sync(0xffffffffu,Z,off);
        float inv=1.0f/Z;
#pragma unroll
        for (int q=0;q<12;++q) sS[w*384+q*32+l]=vals[q]*inv;
    }
    __syncthreads();

    // ---- phase 3: attn-weighted sums ----
    {
        int w = tp, l = to, h2l = l>>2;
        float aw0[8], aw1[8]; float4 ov = make_float4(0,0,0,0);
#pragma unroll
        for (int h=0;h<8;++h){ aw0[h]=0.f; aw1[h]=0.f; }
        for (int jj=0; jj<48; ++jj){
            int j=w*48+jj;
            float ah[8];
#pragma unroll
            for (int h=0;h<8;++h) ah[h]=sS[h*384+j];
            float2 av = ((const float2*)(adj_i + (size_t)j*64))[l];
#pragma unroll
            for (int h=0;h<8;++h){ aw0[h]+=ah[h]*av.x; aw1[h]+=ah[h]*av.y; }
            float4 vv = ((const float4*)(g_vn + (size_t)(b*384+j)*128))[l];
            float a = ah[h2l];
            ov.x+=a*vv.x; ov.y+=a*vv.y; ov.z+=a*vv.z; ov.w+=a*vv.w;
        }
#pragma unroll
        for (int h=0;h<8;++h){ sAW[(w*8+h)*64 + 2*l]=aw0[h]; sAW[(w*8+h)*64 + 2*l+1]=aw1[h]; }
        ((float4*)(sOV + w*128))[l]=ov;
    }
    __syncthreads();
    for (int idx=tid; idx<512; idx+=256){
        float s=0.f;
#pragma unroll
        for (int w2=0;w2<8;++w2) s+=sAW[w2*512+idx];
        sTOT[idx]=s;
    }
    if (tid<128){
        float s=0.f;
#pragma unroll
        for (int w2=0;w2<8;++w2) s+=sOV[w2*128+tid];
        sOVT[tid]=s;
    }
    __syncthreads();
    if (tid<128){
        int h=tid>>4;
        float acc=sOVT[tid];
#pragma unroll 8
        for (int c=0;c<64;++c){
            int cc=(c+tid)&63;
            acc += sWV[tid*64+cc]*sTOT[h*64+cc];
        }
        g_ao[(size_t)bi*128 + (tid&15)*8 + h] = acc;
    }
}

// ============ k_node: 8 rows/CTA, staged weights, 4-row blocking ============
#define NODE_SMEM (40160*4)
__global__ void __launch_bounds__(256) k_node(const float* __restrict__ x,
    const float* __restrict__ nfc1_w, const float* __restrict__ nfc1_b,
    const float* __restrict__ ln1_g, const float* __restrict__ ln1_b,
    const float* __restrict__ nfc2_w, const float* __restrict__ nfc2_b,
    const float* __restrict__ nfc3_w, const float* __restrict__ nfc3_b,
    const float* __restrict__ ln2_g, const float* __restrict__ ln2_b,
    const float* __restrict__ efc1_w, float* __restrict__ out_x){
    extern __shared__ float sm[];
    float* sW  = sm;            // up to 33792
    float* sao = sm + 33792;    // 8*132
    float* sx  = sm + 34848;
    float* sx1 = sm + 35904;
    float* sh  = sm + 36960;    // 8*260
    float* sx2 = sm + 39040;
    float* sred= sm + 40096;    // 64
    int tid = threadIdx.x;
    int o = tid&127, g = tid>>7;
    int l = tid&31, wg = (tid>>5)&3;
    int r0 = blockIdx.x*8;
    for (int idx=tid; idx<256; idx+=256){}
    { int r = tid>>5, c4 = tid&31;
      *(float4*)(sx  + r*132 + c4*4) = *(const float4*)(x    + (size_t)(r0+r)*128 + c4*4);
      *(float4*)(sao + r*132 + c4*4) = *(const float4*)(g_ao + (size_t)(r0+r)*128 + c4*4); }
    // stage 1: nfc1 + LN1
    for (int idx=tid; idx<4096; idx+=256){
        int oo=idx>>5, c4=idx&31;
        *(float4*)(sW + oo*132 + c4*4) = *(const float4*)(nfc1_w + oo*128 + c4*4);
    }
    __syncthreads();
    float val[4];
    {
        float acc[4]; float bv = __ldg(&nfc1_b[o]);
#pragma unroll
        for (int rr=0;rr<4;++rr) acc[rr]=bv;
#pragma unroll 4
        for (int c4=0;c4<32;++c4){
            float4 w = *(const float4*)(sW + o*132 + c4*4);
#pragma unroll
            for (int rr=0;rr<4;++rr){
                float4 a = *(const float4*)(sao + (g*4+rr)*132 + c4*4);
                acc[rr] += w.x*a.x+w.y*a.y+w.z*a.z+w.w*a.w;
            }
        }
#pragma unroll
        for (int rr=0;rr<4;++rr) val[rr] = sx[(g*4+rr)*132+o] + acc[rr];
    }
#pragma unroll
    for (int rr=0;rr<4;++rr){
        float s=val[rr], s2=val[rr]*val[rr];
#pragma unroll
        for (int off=16;off;off>>=1){ s+=__shfl_xor_sync(0xffffffffu,s,off); s2+=__shfl_xor_sync(0xffffffffu,s2,off); }
        if (l==0){ sred[(g*4+rr)*8 + wg*2]=s; sred[(g*4+rr)*8 + wg*2+1]=s2; }
    }
    __syncthreads();
#pragma unroll
    for (int rr=0;rr<4;++rr){
        int r = g*4+rr;
        float S = sred[r*8]+sred[r*8+2]+sred[r*8+4]+sred[r*8+6];
        float S2= sred[r*8+1]+sred[r*8+3]+sred[r*8+5]+sred[r*8+7];
        float m = S*(1.f/128.f), var = S2*(1.f/128.f)-m*m, rs = rsqrtf(var+EPSF);
        sx1[r*132+o] = (val[rr]-m)*rs*__ldg(&ln1_g[o])+__ldg(&ln1_b[o]);
    }
    __syncthreads();
    // stage 2: nfc2 + relu
    for (int idx=tid; idx<8192; idx+=256){
        int oo=idx>>5, c4=idx&31;
        *(float4*)(sW + oo*132 + c4*4) = *(const float4*)(nfc2_w + oo*128 + c4*4);
    }
    __syncthreads();
    {
        float a0[4], a1[4];
        float b0=__ldg(&nfc2_b[o]), b1=__ldg(&nfc2_b[o+128]);
#pragma unroll
        for (int rr=0;rr<4;++rr){ a0[rr]=b0; a1[rr]=b1; }
#pragma unroll 4
        for (int c4=0;c4<32;++c4){
            float4 w0 = *(const float4*)(sW + o*132 + c4*4);
            float4 w1 = *(const float4*)(sW + (o+128)*132 + c4*4);
#pragma unroll
            for (int rr=0;rr<4;++rr){
                float4 a = *(const float4*)(sx1 + (g*4+rr)*132 + c4*4);
                a0[rr] += w0.x*a.x+w0.y*a.y+w0.z*a.z+w0.w*a.w;
                a1[rr] += w1.x*a.x+w1.y*a.y+w1.z*a.z+w1.w*a.w;
            }
        }
#pragma unroll
        for (int rr=0;rr<4;++rr){
            sh[(g*4+rr)*260 + o]       = fmaxf(a0[rr],0.f);
            sh[(g*4+rr)*260 + 128 + o] = fmaxf(a1[rr],0.f);
        }
    }
    __syncthreads();
    // stage 3: nfc3 + LN2
    for (int idx=tid; idx<8192; idx+=256){
        int oo=idx>>6, c4=idx&63;
        *(float4*)(sW + oo*260 + c4*4) = *(const float4*)(nfc3_w + oo*256 + c4*4);
    }
    __syncthreads();
    {
        float acc[4]; float bv=__ldg(&nfc3_b[o]);
#pragma unroll
        for (int rr=0;rr<4;++rr) acc[rr]=bv;
#pragma unroll 4
        for (int c4=0;c4<64;++c4){
            float4 w = *(const float4*)(sW + o*260 + c4*4);
#pragma unroll
            for (int rr=0;rr<4;++rr){
                float4 a = *(const float4*)(sh + (g*4+rr)*260 + c4*4);
                acc[rr] += w.x*a.x+w.y*a.y+w.z*a.z+w.w*a.w;
            }
        }
#pragma unroll
        for (int rr=0;rr<4;++rr) val[rr] = sx1[(g*4+rr)*132+o] + acc[rr];
    }
#pragma unroll
    for (int rr=0;rr<4;++rr){
        float s=val[rr], s2=val[rr]*val[rr];
#pragma unroll
        for (int off=16;off;off>>=1){ s+=__shfl_xor_sync(0xffffffffu,s,off); s2+=__shfl_xor_sync(0xffffffffu,s2,off); }
        if (l==0){ sred[(g*4+rr)*8 + wg*2]=s; sred[(g*4+rr)*8 + wg*2+1]=s2; }
    }
    __syncthreads();
#pragma unroll
    for (int rr=0;rr<4;++rr){
        int r = g*4+rr;
        float S = sred[r*8]+sred[r*8+2]+sred[r*8+4]+sred[r*8+6];
        float S2= sred[r*8+1]+sred[r*8+3]+sred[r*8+5]+sred[r*8+7];
        float m = S*(1.f/128.f), var = S2*(1.f/128.f)-m*m, rs = rsqrtf(var+EPSF);
        float x2v = (val[rr]-m)*rs*__ldg(&ln2_g[o])+__ldg(&ln2_b[o]);
        sx2[r*132+o] = x2v;
        out_x[(size_t)(r0+r)*128+o] = x2v;
    }
    __syncthreads();
    // stage 4: Pc/Pd
    for (int idx=tid; idx<4096; idx+=256){
        int o2=idx>>5, c4=idx&31;
        float4 v = (o2<64) ? *(const float4*)(efc1_w + o2*384 + 128 + c4*4)
                           : *(const float4*)(efc1_w + (o2-64)*384 + 256 + c4*4);
        *(float4*)(sW + o2*132 + c4*4) = v;
    }
    __syncthreads();
    {
        float acc[4]={0,0,0,0};
#pragma unroll 4
        for (int c4=0;c4<32;++c4){
            float4 w = *(const float4*)(sW + o*132 + c4*4);
#pragma unroll
            for (int rr=0;rr<4;++rr){
                float4 a = *(const float4*)(sx2 + (g*4+rr)*132 + c4*4);
                acc[rr] += w.x*a.x+w.y*a.y+w.z*a.z+w.w*a.w;
            }
        }
#pragma unroll
        for (int rr=0;rr<4;++rr){
            int r = r0 + g*4 + rr;
            if (o<64) g_Pc[(size_t)r*64+o]=acc[rr];
            else      g_Pd[(size_t)r*64+(o-64)]=acc[rr];
        }
    }
}

// ============ k_edge: CTA = (b,i,64-j tile), tiled GEMM chain ============
// float offsets: W1a 0 | W1b 4352 | W2 8704 | W3 13056(8704) | W4lo 21760 | W4hi 26112
//  | AI/H3lo 30464 | AJ/H1/OUT 34816 | PC/H3hi 39168 | Y 43520 | sB 47872(640)  => 48512
#define EDGE_SMEM (48512*4)
__device__ __forceinline__ void gemm64(const float* __restrict__ sA, const float* __restrict__ sW,
                                       float acc[4][4], int tp, int to){
#pragma unroll 4
    for (int c4=0;c4<16;++c4){
        float4 a[4], w[4];
#pragma unroll
        for (int k=0;k<4;++k) a[k] = *(const float4*)(sA + (tp*4+k)*68 + c4*4);
#pragma unroll
        for (int k=0;k<4;++k) w[k] = *(const float4*)(sW + (k*16+to)*68 + c4*4);
#pragma unroll
        for (int p=0;p<4;++p)
#pragma unroll
            for (int oo=0;oo<4;++oo)
                acc[p][oo] += a[p].x*w[oo].x + a[p].y*w[oo].y + a[p].z*w[oo].z + a[p].w*w[oo].w;
    }
}

__global__ void __launch_bounds__(256) k_edge(const float* __restrict__ adj,
    const float* __restrict__ efc1_w, const float* __restrict__ efc1_b,
    const float* __restrict__ efc2_w, const float* __restrict__ efc2_b,
    const float* __restrict__ eg1, const float* __restrict__ eb1,
    const float* __restrict__ efc3_w, const float* __restrict__ efc3_b,
    const float* __restrict__ efc4_w, const float* __restrict__ efc4_b,
    const float* __restrict__ eg2, const float* __restrict__ eb2,
    float* __restrict__ out_adj){
    extern __shared__ float sm[];
    float* sW1a = sm;
    float* sW1b = sm + 4352;
    float* sW2  = sm + 8704;
    float* sW3  = sm + 13056;
    float* sW4lo= sm + 21760;
    float* sW4hi= sm + 26112;
    float* sAI  = sm + 30464;  // later H3lo
    float* sAJ  = sm + 34816;  // later H1, later OUT
    float* sPC  = sm + 39168;  // later H3hi
    float* sY   = sm + 43520;
    float* sB   = sm + 47872;
    int tid = threadIdx.x;
    int to = tid&15, tp = tid>>4;
    int bx = blockIdx.x;
    int bi = bx/6, jt = bx - bi*6;
    int b = bi/384, i = bi - b*384;
    int j0 = jt*64;
    const float* adjb = adj + (size_t)b*9437184;

    // weights (float4, padded stride 68)
    for (int idx=tid; idx<1024; idx+=256){
        int o = idx>>4, c4 = idx&15;
        *(float4*)(sW1a + o*68 + c4*4) = *(const float4*)(efc1_w + o*384 + c4*4);
        *(float4*)(sW1b + o*68 + c4*4) = *(const float4*)(efc1_w + o*384 + 64 + c4*4);
        *(float4*)(sW2  + o*68 + c4*4) = *(const float4*)(efc2_w + o*64 + c4*4);
        *(float4*)(sW4lo+ o*68 + c4*4) = *(const float4*)(efc4_w + o*128 + c4*4);
        *(float4*)(sW4hi+ o*68 + c4*4) = *(const float4*)(efc4_w + o*128 + 64 + c4*4);
    }
    for (int idx=tid; idx<2048; idx+=256){
        int o = idx>>4, c4 = idx&15;
        *(float4*)(sW3 + o*68 + c4*4) = *(const float4*)(efc3_w + o*64 + c4*4);
    }
    // activations
    for (int idx=tid; idx<1024; idx+=256){
        int p = idx>>4, c4 = idx&15;
        *(float4*)(sAI + p*68 + c4*4) = *(const float4*)(adjb + ((size_t)i*384 + j0+p)*64 + c4*4);
        *(float4*)(sAJ + p*68 + c4*4) = *(const float4*)(adjb + ((size_t)(j0+p)*384 + i)*64 + c4*4);
        *(float4*)(sPC + p*68 + c4*4) = *(const float4*)(g_Pc + (size_t)(b*384 + j0+p)*64 + c4*4);
    }
    if (tid<64){
        sB[tid]=efc1_b[tid]; sB[64+tid]=efc2_b[tid]; sB[128+tid]=efc4_b[tid];
        sB[192+tid]=eg1[tid]; sB[256+tid]=eb1[tid]; sB[320+tid]=eg2[tid]; sB[384+tid]=eb2[tid];
        sB[576+tid]=g_Pd[(size_t)bi*64+tid];
    }
    if (tid<128) sB[448+tid]=efc3_b[tid];
    __syncthreads();

    float acc[4][4];
    // ---- stage 1: h1 = relu(Wa*ai + Wb*aj + pc + pd + b1) ----
#pragma unroll
    for (int p=0;p<4;++p)
#pragma unroll
        for (int oo=0;oo<4;++oo) acc[p][oo]=0.f;
    gemm64(sAI, sW1a, acc, tp, to);
    gemm64(sAJ, sW1b, acc, tp, to);
    __syncthreads();   // all reads of sAJ done
    float* sH1 = sAJ;
#pragma unroll
    for (int p=0;p<4;++p){
        int pr = tp*4+p;
#pragma unroll
        for (int oo=0;oo<4;++oo){
            int o = oo*16+to;
            float h = acc[p][oo] + sB[o] + sB[576+o] + sPC[pr*68+o];
            sH1[pr*68+o] = fmaxf(h, 0.f);
        }
    }
    __syncthreads();
    // ---- stage 2: adj1 = LN(ai + W2*h1 + b2) ----
#pragma unroll
    for (int p=0;p<4;++p)
#pragma unroll
        for (int oo=0;oo<4;++oo) acc[p][oo]=0.f;
    gemm64(sH1, sW2, acc, tp, to);
    float yreg[4][4];
#pragma unroll
    for (int p=0;p<4;++p){
        int pr = tp*4+p;
        float v[4], s=0.f, s2=0.f;
#pragma unroll
        for (int oo=0;oo<4;++oo){
            int o = oo*16+to;
            v[oo] = acc[p][oo] + sB[64+o] + sAI[pr*68+o];
            s += v[oo]; s2 += v[oo]*v[oo];
        }
        s  += __shfl_xor_sync(0xffffffffu,s,1);  s2 += __shfl_xor_sync(0xffffffffu,s2,1);
        s  += __shfl_xor_sync(0xffffffffu,s,2);  s2 += __shfl_xor_sync(0xffffffffu,s2,2);
        s  += __shfl_xor_sync(0xffffffffu,s,4);  s2 += __shfl_xor_sync(0xffffffffu,s2,4);
        s  += __shfl_xor_sync(0xffffffffu,s,8);  s2 += __shfl_xor_sync(0xffffffffu,s2,8);
        float m = s*(1.f/64.f), var = s2*(1.f/64.f)-m*m, rs = rsqrtf(var+EPSF);
#pragma unroll
        for (int oo=0;oo<4;++oo){
            int o = oo*16+to;
            yreg[p][oo] = (v[oo]-m)*rs*sB[192+o]+sB[256+o];
            sY[pr*68+o] = yreg[p][oo];
        }
    }
    __syncthreads();
    // ---- stage 3: h3 = relu(W3*adj1 + b3), 128 outs in two passes ----
    float* sH3lo = sAI;
    float* sH3hi = sPC;
#pragma unroll
    for (int p=0;p<4;++p)
#pragma unroll
        for (int oo=0;oo<4;++oo) acc[p][oo]=0.f;
    gemm64(sY, sW3, acc, tp, to);
#pragma unroll
    for (int p=0;p<4;++p){
        int pr = tp*4+p;
#pragma unroll
        for (int oo=0;oo<4;++oo){
            int o = oo*16+to;
            sH3lo[pr*68+o] = fmaxf(acc[p][oo] + sB[448+o], 0.f);
        }
    }
#pragma unroll
    for (int p=0;p<4;++p)
#pragma unroll
        for (int oo=0;oo<4;++oo) acc[p][oo]=0.f;
    gemm64(sY, sW3 + 64*68, acc, tp, to);
#pragma unroll
    for (int p=0;p<4;++p){
        int pr = tp*4+p;
#pragma unroll
        for (int oo=0;oo<4;++oo){
            int o = oo*16+to;
            sH3hi[pr*68+o] = fmaxf(acc[p][oo] + sB[448+64+o], 0.f);
        }
    }
    __syncthreads();
    // ---- stage 4: out = LN(adj1 + W4*h3 + b4) ----
#pragma unroll
    for (int p=0;p<4;++p)
#pragma unroll
        for (int oo=0;oo<4;++oo) acc[p][oo]=0.f;
    gemm64(sH3lo, sW4lo, acc, tp, to);
    gemm64(sH3hi, sW4hi, acc, tp, to);
    float* sOut = sAJ;
#pragma unroll
    for (int p=0;p<4;++p){
        int pr = tp*4+p;
        float v[4], s=0.f, s2=0.f;
#pragma unroll
        for (int oo=0;oo<4;++oo){
            int o = oo*16+to;
            v[oo] = acc[p][oo] + sB[128+o] + yreg[p][oo];
            s += v[oo]; s2 += v[oo]*v[oo];
        }
        s  += __shfl_xor_sync(0xffffffffu,s,1);  s2 += __shfl_xor_sync(0xffffffffu,s2,1);
        s  += __shfl_xor_sync(0xffffffffu,s,2);  s2 += __shfl_xor_sync(0xffffffffu,s2,2);
        s  += __shfl_xor_sync(0xffffffffu,s,4);  s2 += __shfl_xor_sync(0xffffffffu,s2,4);
        s  += __shfl_xor_sync(0xffffffffu,s,8);  s2 += __shfl_xor_sync(0xffffffffu,s2,8);
        float m = s*(1.f/64.f), var = s2*(1.f/64.f)-m*m, rs = rsqrtf(var+EPSF);
#pragma unroll
        for (int oo=0;oo<4;++oo){
            int o = oo*16+to;
            sOut[pr*68+o] = (v[oo]-m)*rs*sB[320+o]+sB[384+o];
        }
    }
    __syncthreads();
    for (int idx=tid; idx<1024; idx+=256){
        int p = idx>>4, c4 = idx&15;
        *(float4*)(out_adj + ((size_t)bi*384 + j0+p)*64 + c4*4) = *(const float4*)(sOut + p*68 + c4*4);
    }
}

extern "C" void kernel_launch(void* const* d_in, const int* in_sizes, int n_in,
                              void* d_out, int out_size){
    const float* x       = (const float*)d_in[0];
    const float* adj     = (const float*)d_in[1];
    const float* wnq     = (const float*)d_in[2];
    const float* wnk     = (const float*)d_in[3];
    const float* wnv     = (const float*)d_in[4];
    const float* weq     = (const float*)d_in[5];
    const float* wek     = (const float*)d_in[6];
    const float* wev     = (const float*)d_in[7];
    const float* nfc1_w  = (const float*)d_in[8];
    const float* nfc1_b  = (const float*)d_in[9];
    const float* ln1_g   = (const float*)d_in[10];
    const float* ln1_b   = (const float*)d_in[11];
    const float* nfc2_w  = (const float*)d_in[12];
    const float* nfc2_b  = (const float*)d_in[13];
    const float* nfc3_w  = (const float*)d_in[14];
    const float* nfc3_b  = (const float*)d_in[15];
    const float* ln2_g   = (const float*)d_in[16];
    const float* ln2_b   = (const float*)d_in[17];
    const float* efc1_w  = (const float*)d_in[18];
    const float* efc1_b  = (const float*)d_in[19];
    const float* efc2_w  = (const float*)d_in[20];
    const float* efc2_b  = (const float*)d_in[21];
    const float* eln1_g  = (const float*)d_in[22];
    const float* eln1_b  = (const float*)d_in[23];
    const float* efc3_w  = (const float*)d_in[24];
    const float* efc3_b  = (const float*)d_in[25];
    const float* efc4_w  = (const float*)d_in[26];
    const float* efc4_b  = (const float*)d_in[27];
    const float* eln2_g  = (const float*)d_in[28];
    const float* eln2_b  = (const float*)d_in[29];
    float* out_x   = (float*)d_out;
    float* out_adj = out_x + 2*384*128;

    static int configured = 0;
    cudaFuncSetAttribute(k_qkv,  cudaFuncAttributeMaxDynamicSharedMemorySize, QKV_SMEM);
    cudaFuncSetAttribute(k_attn, cudaFuncAttributeMaxDynamicSharedMemorySize, ATTN_SMEM);
    cudaFuncSetAttribute(k_node, cudaFuncAttributeMaxDynamicSharedMemorySize, NODE_SMEM);
    cudaFuncSetAttribute(k_edge, cudaFuncAttributeMaxDynamicSharedMemorySize, EDGE_SMEM);
    (void)configured;

    k_qkv<<<96,256,QKV_SMEM>>>(x, wnq, wnk, wnv);
    k_attn<<<768,256,ATTN_SMEM>>>(adj, weq, wek, wev);
    k_node<<<96,256,NODE_SMEM>>>(x, nfc1_w, nfc1_b, ln1_g, ln1_b, nfc2_w, nfc2_b,
                                 nfc3_w, nfc3_b, ln2_g, ln2_b, efc1_w, out_x);
    k_edge<<<4608,256,EDGE_SMEM>>>(adj, efc1_w, efc1_b, efc2_w, efc2_b,
                                   eln1_g, eln1_b, efc3_w, efc3_b,
                                   efc4_w, efc4_b, eln2_g, eln2_b, out_adj);
}

// round 6
// speedup vs baseline: 4.6988x; 1.1024x over previous
#include <cuda_runtime.h>
#include <cstdint>

#define EPSF 1e-5f
#define SCALE 0.17677669529663687f

// scratch
__device__ float g_qn[2*384*128];
__device__ float g_kn[2*384*128];
__device__ float g_vn[2*384*128];
__device__ float g_ao[2*384*128];
__device__ float g_Pc[2*384*64];
__device__ float g_Pd[2*384*64];

// ============ k_qkv: 8 rows/CTA, smem-staged weights, 4-row blocking ============
#define QKV_SMEM (51744*4)
__global__ void __launch_bounds__(256) k_qkv(const float* __restrict__ x,
    const float* __restrict__ wnq, const float* __restrict__ wnk, const float* __restrict__ wnv){
    extern __shared__ float sm[];
    float* sWq = sm;             // 128*132
    float* sWk = sm + 16896;
    float* sWv = sm + 33792;
    float* sX  = sm + 50688;     // 8*132
    int tid = threadIdx.x;
    for (int idx=tid; idx<4096; idx+=256){
        int o = idx>>5, c4 = idx&31;
        *(float4*)(sWq + o*132 + c4*4) = *(const float4*)(wnq + o*128 + c4*4);
        *(float4*)(sWk + o*132 + c4*4) = *(const float4*)(wnk + o*128 + c4*4);
        *(float4*)(sWv + o*132 + c4*4) = *(const float4*)(wnv + o*128 + c4*4);
    }
    int r0 = blockIdx.x*8;
    { int r = tid>>5, c4 = tid&31;
      *(float4*)(sX + r*132 + c4*4) = *(const float4*)(x + (size_t)(r0+r)*128 + c4*4); }
    __syncthreads();
    int o = tid&127, g = tid>>7;
    float aq[4]={0,0,0,0}, ak[4]={0,0,0,0}, av[4]={0,0,0,0};
#pragma unroll 4
    for (int c4=0;c4<32;++c4){
        float4 wq = *(const float4*)(sWq + o*132 + c4*4);
        float4 wk = *(const float4*)(sWk + o*132 + c4*4);
        float4 wv = *(const float4*)(sWv + o*132 + c4*4);
#pragma unroll
        for (int rr=0;rr<4;++rr){
            float4 a = *(const float4*)(sX + (g*4+rr)*132 + c4*4);
            aq[rr] += wq.x*a.x+wq.y*a.y+wq.z*a.z+wq.w*a.w;
            ak[rr] += wk.x*a.x+wk.y*a.y+wk.z*a.z+wk.w*a.w;
            av[rr] += wv.x*a.x+wv.y*a.y+wv.z*a.z+wv.w*a.w;
        }
    }
#pragma unroll
    for (int rr=0;rr<4;++rr){
        int r = r0 + g*4 + rr;
        g_qn[r*128+o]=aq[rr]; g_kn[r*128+o]=ak[rr]; g_vn[r*128+o]=av[rr];
    }
}

// ============ k_attn: one CTA per (b,i) ============
#define ATTN_SMEM (22784*4)
__global__ void __launch_bounds__(256) k_attn(const float* __restrict__ adj,
    const float* __restrict__ weq, const float* __restrict__ wek, const float* __restrict__ wev){
    extern __shared__ float sm[];
    float* sW = sm;
    float* sA = sm + 17408;
    float* sS = sm + 19584;
    float* sQ = sm + 22656;
    int bi = blockIdx.x, b = bi/384;
    int tid = threadIdx.x;
    int to = tid&31, tp = tid>>5;      // tp = warp id
    for (int idx=tid; idx<4096; idx+=256){
        int o = idx>>4, c4 = idx&15;
        float4 v = (o<128) ? *(const float4*)(weq + o*64 + c4*4)
                           : *(const float4*)(wek + (o-128)*64 + c4*4);
        *(float4*)(sW + o*68 + c4*4) = v;
    }
    if (tid<128) sQ[tid] = g_qn[(size_t)bi*128 + tid];
    const float* adj_i = adj + (size_t)bi*24576;
    __syncthreads();

    // ---- phase 1: eq/ek GEMM + scores ----
    for (int jt=0; jt<12; ++jt){
        int j0 = jt*32;
        for (int idx=tid; idx<512; idx+=256){
            int p = idx>>4, c4 = idx&15;
            *(float4*)(sA + p*68 + c4*4) = *(const float4*)(adj_i + (size_t)(j0+p)*64 + c4*4);
        }
        __syncthreads();
        float acc[4][8];
#pragma unroll
        for (int p=0;p<4;++p)
#pragma unroll
            for (int o=0;o<8;++o) acc[p][o]=0.f;
#pragma unroll 2
        for (int c4=0;c4<16;++c4){
            float4 a[4], w[8];
#pragma unroll
            for (int k=0;k<4;++k) a[k] = *(const float4*)(sA + (tp*4+k)*68 + c4*4);
#pragma unroll
            for (int k=0;k<8;++k) w[k] = *(const float4*)(sW + (k*32+to)*68 + c4*4);
#pragma unroll
            for (int p=0;p<4;++p)
#pragma unroll
                for (int o=0;o<8;++o)
                    acc[p][o] += a[p].x*w[o].x + a[p].y*w[o].y + a[p].z*w[o].z + a[p].w*w[o].w;
        }
#pragma unroll
        for (int pp=0;pp<4;++pp){
            int j = j0 + tp*4 + pp;
            const float* kr = g_kn + (size_t)(b*384+j)*128;
#pragma unroll
            for (int m=0;m<4;++m){
                int d = m*32 + to;
                float eq = sQ[d] + acc[pp][m];
                float ek = __ldg(&kr[d]) + acc[pp][m+4];
                float pr = eq*ek;
                pr += __shfl_xor_sync(0xffffffffu, pr, 1);
                pr += __shfl_xor_sync(0xffffffffu, pr, 2);
                pr += __shfl_xor_sync(0xffffffffu, pr, 4);
                pr += __shfl_xor_sync(0xffffffffu, pr, 8);
                if ((to&15)==0) sS[(2*m + (to>>4))*384 + j] = pr*SCALE;
            }
        }
        __syncthreads();
    }

    float* sWV = sm;
    float* sAW = sm + 8192;
    float* sOV = sm + 12288;
    float* sTOT= sm + 13312;
    float* sOVT= sm + 13824;
    for (int idx=tid; idx<8192; idx+=256) sWV[idx]=wev[idx];
    __syncthreads();

    // ---- phase 2: softmax, warp = head ----
    {
        int w = tp, l = to;
        float vals[12]; float m=-1e30f;
#pragma unroll
        for (int q=0;q<12;++q){ vals[q]=sS[w*384+q*32+l]; m=fmaxf(m,vals[q]); }
#pragma unroll
        for (int off=16;off;off>>=1) m=fmaxf(m,__shfl_xor_sync(0xffffffffu,m,off));
        float Z=0.f;
#pragma unroll
        for (int q=0;q<12;++q){ vals[q]=__expf(vals[q]-m); Z+=vals[q]; }
#pragma unroll
        for (int off=16;off;off>>=1) Z+=__shfl_xor_sync(0xffffffffu,Z,off);
        float inv=1.0f/Z;
#pragma unroll
        for (int q=0;q<12;++q) sS[w*384+q*32+l]=vals[q]*inv;
    }
    __syncthreads();

    // ---- phase 3: attn-weighted sums ----
    {
        int w = tp, l = to, h2l = l>>2;
        float aw0[8], aw1[8]; float4 ov = make_float4(0,0,0,0);
#pragma unroll
        for (int h=0;h<8;++h){ aw0[h]=0.f; aw1[h]=0.f; }
        for (int jj=0; jj<48; ++jj){
            int j=w*48+jj;
            float ah[8];
#pragma unroll
            for (int h=0;h<8;++h) ah[h]=sS[h*384+j];
            float2 av = ((const float2*)(adj_i + (size_t)j*64))[l];
#pragma unroll
            for (int h=0;h<8;++h){ aw0[h]+=ah[h]*av.x; aw1[h]+=ah[h]*av.y; }
            float4 vv = ((const float4*)(g_vn + (size_t)(b*384+j)*128))[l];
            float a = ah[h2l];
            ov.x+=a*vv.x; ov.y+=a*vv.y; ov.z+=a*vv.z; ov.w+=a*vv.w;
        }
#pragma unroll
        for (int h=0;h<8;++h){ sAW[(w*8+h)*64 + 2*l]=aw0[h]; sAW[(w*8+h)*64 + 2*l+1]=aw1[h]; }
        ((float4*)(sOV + w*128))[l]=ov;
    }
    __syncthreads();
    for (int idx=tid; idx<512; idx+=256){
        float s=0.f;
#pragma unroll
        for (int w2=0;w2<8;++w2) s+=sAW[w2*512+idx];
        sTOT[idx]=s;
    }
    if (tid<128){
        float s=0.f;
#pragma unroll
        for (int w2=0;w2<8;++w2) s+=sOV[w2*128+tid];
        sOVT[tid]=s;
    }
    __syncthreads();
    if (tid<128){
        int h=tid>>4;
        float acc=sOVT[tid];
#pragma unroll 8
        for (int c=0;c<64;++c){
            int cc=(c+tid)&63;
            acc += sWV[tid*64+cc]*sTOT[h*64+cc];
        }
        g_ao[(size_t)bi*128 + (tid&15)*8 + h] = acc;
    }
}

// ============ k_node: 8 rows/CTA, staged weights, 4-row blocking ============
#define NODE_SMEM (40160*4)
__global__ void __launch_bounds__(256) k_node(const float* __restrict__ x,
    const float* __restrict__ nfc1_w, const float* __restrict__ nfc1_b,
    const float* __restrict__ ln1_g, const float* __restrict__ ln1_b,
    const float* __restrict__ nfc2_w, const float* __restrict__ nfc2_b,
    const float* __restrict__ nfc3_w, const float* __restrict__ nfc3_b,
    const float* __restrict__ ln2_g, const float* __restrict__ ln2_b,
    const float* __restrict__ efc1_w, float* __restrict__ out_x){
    extern __shared__ float sm[];
    float* sW  = sm;
    float* sao = sm + 33792;
    float* sx  = sm + 34848;
    float* sx1 = sm + 35904;
    float* sh  = sm + 36960;
    float* sx2 = sm + 39040;
    float* sred= sm + 40096;
    int tid = threadIdx.x;
    int o = tid&127, g = tid>>7;
    int l = tid&31, wg = (tid>>5)&3;
    int r0 = blockIdx.x*8;
    { int r = tid>>5, c4 = tid&31;
      *(float4*)(sx  + r*132 + c4*4) = *(const float4*)(x    + (size_t)(r0+r)*128 + c4*4);
      *(float4*)(sao + r*132 + c4*4) = *(const float4*)(g_ao + (size_t)(r0+r)*128 + c4*4); }
    for (int idx=tid; idx<4096; idx+=256){
        int oo=idx>>5, c4=idx&31;
        *(float4*)(sW + oo*132 + c4*4) = *(const float4*)(nfc1_w + oo*128 + c4*4);
    }
    __syncthreads();
    float val[4];
    {
        float acc[4]; float bv = __ldg(&nfc1_b[o]);
#pragma unroll
        for (int rr=0;rr<4;++rr) acc[rr]=bv;
#pragma unroll 4
        for (int c4=0;c4<32;++c4){
            float4 w = *(const float4*)(sW + o*132 + c4*4);
#pragma unroll
            for (int rr=0;rr<4;++rr){
                float4 a = *(const float4*)(sao + (g*4+rr)*132 + c4*4);
                acc[rr] += w.x*a.x+w.y*a.y+w.z*a.z+w.w*a.w;
            }
        }
#pragma unroll
        for (int rr=0;rr<4;++rr) val[rr] = sx[(g*4+rr)*132+o] + acc[rr];
    }
#pragma unroll
    for (int rr=0;rr<4;++rr){
        float s=val[rr], s2=val[rr]*val[rr];
#pragma unroll
        for (int off=16;off;off>>=1){ s+=__shfl_xor_sync(0xffffffffu,s,off); s2+=__shfl_xor_sync(0xffffffffu,s2,off); }
        if (l==0){ sred[(g*4+rr)*8 + wg*2]=s; sred[(g*4+rr)*8 + wg*2+1]=s2; }
    }
    __syncthreads();
#pragma unroll
    for (int rr=0;rr<4;++rr){
        int r = g*4+rr;
        float S = sred[r*8]+sred[r*8+2]+sred[r*8+4]+sred[r*8+6];
        float S2= sred[r*8+1]+sred[r*8+3]+sred[r*8+5]+sred[r*8+7];
        float m = S*(1.f/128.f), var = S2*(1.f/128.f)-m*m, rs = rsqrtf(var+EPSF);
        sx1[r*132+o] = (val[rr]-m)*rs*__ldg(&ln1_g[o])+__ldg(&ln1_b[o]);
    }
    __syncthreads();
    for (int idx=tid; idx<8192; idx+=256){
        int oo=idx>>5, c4=idx&31;
        *(float4*)(sW + oo*132 + c4*4) = *(const float4*)(nfc2_w + oo*128 + c4*4);
    }
    __syncthreads();
    {
        float a0[4], a1[4];
        float b0=__ldg(&nfc2_b[o]), b1=__ldg(&nfc2_b[o+128]);
#pragma unroll
        for (int rr=0;rr<4;++rr){ a0[rr]=b0; a1[rr]=b1; }
#pragma unroll 4
        for (int c4=0;c4<32;++c4){
            float4 w0 = *(const float4*)(sW + o*132 + c4*4);
            float4 w1 = *(const float4*)(sW + (o+128)*132 + c4*4);
#pragma unroll
            for (int rr=0;rr<4;++rr){
                float4 a = *(const float4*)(sx1 + (g*4+rr)*132 + c4*4);
                a0[rr] += w0.x*a.x+w0.y*a.y+w0.z*a.z+w0.w*a.w;
                a1[rr] += w1.x*a.x+w1.y*a.y+w1.z*a.z+w1.w*a.w;
            }
        }
#pragma unroll
        for (int rr=0;rr<4;++rr){
            sh[(g*4+rr)*260 + o]       = fmaxf(a0[rr],0.f);
            sh[(g*4+rr)*260 + 128 + o] = fmaxf(a1[rr],0.f);
        }
    }
    __syncthreads();
    for (int idx=tid; idx<8192; idx+=256){
        int oo=idx>>6, c4=idx&63;
        *(float4*)(sW + oo*260 + c4*4) = *(const float4*)(nfc3_w + oo*256 + c4*4);
    }
    __syncthreads();
    {
        float acc[4]; float bv=__ldg(&nfc3_b[o]);
#pragma unroll
        for (int rr=0;rr<4;++rr) acc[rr]=bv;
#pragma unroll 4
        for (int c4=0;c4<64;++c4){
            float4 w = *(const float4*)(sW + o*260 + c4*4);
#pragma unroll
            for (int rr=0;rr<4;++rr){
                float4 a = *(const float4*)(sh + (g*4+rr)*260 + c4*4);
                acc[rr] += w.x*a.x+w.y*a.y+w.z*a.z+w.w*a.w;
            }
        }
#pragma unroll
        for (int rr=0;rr<4;++rr) val[rr] = sx1[(g*4+rr)*132+o] + acc[rr];
    }
#pragma unroll
    for (int rr=0;rr<4;++rr){
        float s=val[rr], s2=val[rr]*val[rr];
#pragma unroll
        for (int off=16;off;off>>=1){ s+=__shfl_xor_sync(0xffffffffu,s,off); s2+=__shfl_xor_sync(0xffffffffu,s2,off); }
        if (l==0){ sred[(g*4+rr)*8 + wg*2]=s; sred[(g*4+rr)*8 + wg*2+1]=s2; }
    }
    __syncthreads();
#pragma unroll
    for (int rr=0;rr<4;++rr){
        int r = g*4+rr;
        float S = sred[r*8]+sred[r*8+2]+sred[r*8+4]+sred[r*8+6];
        float S2= sred[r*8+1]+sred[r*8+3]+sred[r*8+5]+sred[r*8+7];
        float m = S*(1.f/128.f), var = S2*(1.f/128.f)-m*m, rs = rsqrtf(var+EPSF);
        float x2v = (val[rr]-m)*rs*__ldg(&ln2_g[o])+__ldg(&ln2_b[o]);
        sx2[r*132+o] = x2v;
        out_x[(size_t)(r0+r)*128+o] = x2v;
    }
    __syncthreads();
    for (int idx=tid; idx<4096; idx+=256){
        int o2=idx>>5, c4=idx&31;
        float4 v = (o2<64) ? *(const float4*)(efc1_w + o2*384 + 128 + c4*4)
                           : *(const float4*)(efc1_w + (o2-64)*384 + 256 + c4*4);
        *(float4*)(sW + o2*132 + c4*4) = v;
    }
    __syncthreads();
    {
        float acc[4]={0,0,0,0};
#pragma unroll 4
        for (int c4=0;c4<32;++c4){
            float4 w = *(const float4*)(sW + o*132 + c4*4);
#pragma unroll
            for (int rr=0;rr<4;++rr){
                float4 a = *(const float4*)(sx2 + (g*4+rr)*132 + c4*4);
                acc[rr] += w.x*a.x+w.y*a.y+w.z*a.z+w.w*a.w;
            }
        }
#pragma unroll
        for (int rr=0;rr<4;++rr){
            int r = r0 + g*4 + rr;
            if (o<64) g_Pc[(size_t)r*64+o]=acc[rr];
            else      g_Pd[(size_t)r*64+(o-64)]=acc[rr];
        }
    }
}

// ============ k_edge: phase-split weights for 2 CTAs/SM ============
// floats: sW 8704 @0 | AI 8704 | AJ 13056 | PC 17408 | Y 21760 | sB 26112(640) => 26752 (107KB)
#define EDGE_SMEM (26752*4)
__device__ __forceinline__ void gemm64(const float* __restrict__ sA, const float* __restrict__ sW,
                                       float acc[4][4], int tp, int to){
#pragma unroll 4
    for (int c4=0;c4<16;++c4){
        float4 a[4], w[4];
#pragma unroll
        for (int k=0;k<4;++k) a[k] = *(const float4*)(sA + (tp*4+k)*68 + c4*4);
#pragma unroll
        for (int k=0;k<4;++k) w[k] = *(const float4*)(sW + (k*16+to)*68 + c4*4);
#pragma unroll
        for (int p=0;p<4;++p)
#pragma unroll
            for (int oo=0;oo<4;++oo)
                acc[p][oo] += a[p].x*w[oo].x + a[p].y*w[oo].y + a[p].z*w[oo].z + a[p].w*w[oo].w;
    }
}

__global__ void __launch_bounds__(256) k_edge(const float* __restrict__ adj,
    const float* __restrict__ efc1_w, const float* __restrict__ efc1_b,
    const float* __restrict__ efc2_w, const float* __restrict__ efc2_b,
    const float* __restrict__ eg1, const float* __restrict__ eb1,
    const float* __restrict__ efc3_w, const float* __restrict__ efc3_b,
    const float* __restrict__ efc4_w, const float* __restrict__ efc4_b,
    const float* __restrict__ eg2, const float* __restrict__ eb2,
    float* __restrict__ out_adj){
    extern __shared__ float sm[];
    float* sW   = sm;          // 8704, reloaded per phase
    float* sAI  = sm + 8704;   // later H3lo
    float* sAJ  = sm + 13056;  // later H1, later OUT
    float* sPC  = sm + 17408;  // later H3hi
    float* sY   = sm + 21760;
    float* sB   = sm + 26112;
    int tid = threadIdx.x;
    int to = tid&15, tp = tid>>4;
    int bx = blockIdx.x;
    int bi = bx/6, jt = bx - bi*6;
    int b = bi/384, i = bi - b*384;
    int j0 = jt*64;
    const float* adjb = adj + (size_t)b*9437184;

    // phase A1 weights: W1a @0, W1b @4352
    for (int idx=tid; idx<1024; idx+=256){
        int o = idx>>4, c4 = idx&15;
        *(float4*)(sW        + o*68 + c4*4) = *(const float4*)(efc1_w + o*384 + c4*4);
        *(float4*)(sW + 4352 + o*68 + c4*4) = *(const float4*)(efc1_w + o*384 + 64 + c4*4);
    }
    // activations
    for (int idx=tid; idx<1024; idx+=256){
        int p = idx>>4, c4 = idx&15;
        *(float4*)(sAI + p*68 + c4*4) = *(const float4*)(adjb + ((size_t)i*384 + j0+p)*64 + c4*4);
        *(float4*)(sAJ + p*68 + c4*4) = *(const float4*)(adjb + ((size_t)(j0+p)*384 + i)*64 + c4*4);
        *(float4*)(sPC + p*68 + c4*4) = *(const float4*)(g_Pc + (size_t)(b*384 + j0+p)*64 + c4*4);
    }
    if (tid<64){
        sB[tid]=efc1_b[tid]; sB[64+tid]=efc2_b[tid]; sB[128+tid]=efc4_b[tid];
        sB[192+tid]=eg1[tid]; sB[256+tid]=eb1[tid]; sB[320+tid]=eg2[tid]; sB[384+tid]=eb2[tid];
        sB[576+tid]=g_Pd[(size_t)bi*64+tid];
    }
    if (tid<128) sB[448+tid]=efc3_b[tid];
    __syncthreads();

    float acc[4][4];
    // ---- stage 1: h1 = relu(Wa*ai + Wb*aj + pc + pd + b1) ----
#pragma unroll
    for (int p=0;p<4;++p)
#pragma unroll
        for (int oo=0;oo<4;++oo) acc[p][oo]=0.f;
    gemm64(sAI, sW, acc, tp, to);
    gemm64(sAJ, sW + 4352, acc, tp, to);
    __syncthreads();   // all reads of sAJ + W1 done
    float* sH1 = sAJ;
#pragma unroll
    for (int p=0;p<4;++p){
        int pr = tp*4+p;
#pragma unroll
        for (int oo=0;oo<4;++oo){
            int o = oo*16+to;
            float h = acc[p][oo] + sB[o] + sB[576+o] + sPC[pr*68+o];
            sH1[pr*68+o] = fmaxf(h, 0.f);
        }
    }
    // phase A2 weights: W2 @0 (overwrites W1a; reads finished at sync above)
    for (int idx=tid; idx<1024; idx+=256){
        int o = idx>>4, c4 = idx&15;
        *(float4*)(sW + o*68 + c4*4) = *(const float4*)(efc2_w + o*64 + c4*4);
    }
    __syncthreads();
    // ---- stage 2: adj1 = LN(ai + W2*h1 + b2) ----
#pragma unroll
    for (int p=0;p<4;++p)
#pragma unroll
        for (int oo=0;oo<4;++oo) acc[p][oo]=0.f;
    gemm64(sH1, sW, acc, tp, to);
#pragma unroll
    for (int p=0;p<4;++p){
        int pr = tp*4+p;
        float v[4], s=0.f, s2=0.f;
#pragma unroll
        for (int oo=0;oo<4;++oo){
            int o = oo*16+to;
            v[oo] = acc[p][oo] + sB[64+o] + sAI[pr*68+o];
            s += v[oo]; s2 += v[oo]*v[oo];
        }
        s  += __shfl_xor_sync(0xffffffffu,s,1);  s2 += __shfl_xor_sync(0xffffffffu,s2,1);
        s  += __shfl_xor_sync(0xffffffffu,s,2);  s2 += __shfl_xor_sync(0xffffffffu,s2,2);
        s  += __shfl_xor_sync(0xffffffffu,s,4);  s2 += __shfl_xor_sync(0xffffffffu,s2,4);
        s  += __shfl_xor_sync(0xffffffffu,s,8);  s2 += __shfl_xor_sync(0xffffffffu,s2,8);
        float m = s*(1.f/64.f), var = s2*(1.f/64.f)-m*m, rs = rsqrtf(var+EPSF);
#pragma unroll
        for (int oo=0;oo<4;++oo){
            int o = oo*16+to;
            sY[pr*68+o] = (v[oo]-m)*rs*sB[192+o]+sB[256+o];
        }
    }
    __syncthreads();   // W2/AI reads done, Y written
    // phase B weights: W3 (128 rows)
    for (int idx=tid; idx<2048; idx+=256){
        int o = idx>>4, c4 = idx&15;
        *(float4*)(sW + o*68 + c4*4) = *(const float4*)(efc3_w + o*64 + c4*4);
    }
    __syncthreads();
    // ---- stage 3: h3 = relu(W3*adj1 + b3) ----
    float* sH3lo = sAI;
    float* sH3hi = sPC;
#pragma unroll
    for (int p=0;p<4;++p)
#pragma unroll
        for (int oo=0;oo<4;++oo) acc[p][oo]=0.f;
    gemm64(sY, sW, acc, tp, to);
#pragma unroll
    for (int p=0;p<4;++p){
        int pr = tp*4+p;
#pragma unroll
        for (int oo=0;oo<4;++oo){
            int o = oo*16+to;
            sH3lo[pr*68+o] = fmaxf(acc[p][oo] + sB[448+o], 0.f);
        }
    }
#pragma unroll
    for (int p=0;p<4;++p)
#pragma unroll
        for (int oo=0;oo<4;++oo) acc[p][oo]=0.f;
    gemm64(sY, sW + 64*68, acc, tp, to);
#pragma unroll
    for (int p=0;p<4;++p){
        int pr = tp*4+p;
#pragma unroll
        for (int oo=0;oo<4;++oo){
            int o = oo*16+to;
            sH3hi[pr*68+o] = fmaxf(acc[p][oo] + sB[448+64+o], 0.f);
        }
    }
    __syncthreads();   // W3 reads done, H3 written
    // phase C weights: W4lo @0, W4hi @4352
    for (int idx=tid; idx<1024; idx+=256){
        int o = idx>>4, c4 = idx&15;
        *(float4*)(sW        + o*68 + c4*4) = *(const float4*)(efc4_w + o*128 + c4*4);
        *(float4*)(sW + 4352 + o*68 + c4*4) = *(const float4*)(efc4_w + o*128 + 64 + c4*4);
    }
    __syncthreads();
    // ---- stage 4: out = LN(adj1 + W4*h3 + b4) ----
#pragma unroll
    for (int p=0;p<4;++p)
#pragma unroll
        for (int oo=0;oo<4;++oo) acc[p][oo]=0.f;
    gemm64(sH3lo, sW, acc, tp, to);
    gemm64(sH3hi, sW + 4352, acc, tp, to);
    __syncthreads();   // H1 buffer (sAJ) fully dead; safe to overwrite as sOut
    float* sOut = sAJ;
#pragma unroll
    for (int p=0;p<4;++p){
        int pr = tp*4+p;
        float v[4], s=0.f, s2=0.f;
#pragma unroll
        for (int oo=0;oo<4;++oo){
            int o = oo*16+to;
            v[oo] = acc[p][oo] + sB[128+o] + sY[pr*68+o];
            s += v[oo]; s2 += v[oo]*v[oo];
        }
        s  += __shfl_xor_sync(0xffffffffu,s,1);  s2 += __shfl_xor_sync(0xffffffffu,s2,1);
        s  += __shfl_xor_sync(0xffffffffu,s,2);  s2 += __shfl_xor_sync(0xffffffffu,s2,2);
        s  += __shfl_xor_sync(0xffffffffu,s,4);  s2 += __shfl_xor_sync(0xffffffffu,s2,4);
        s  += __shfl_xor_sync(0xffffffffu,s,8);  s2 += __shfl_xor_sync(0xffffffffu,s2,8);
        float m = s*(1.f/64.f), var = s2*(1.f/64.f)-m*m, rs = rsqrtf(var+EPSF);
#pragma unroll
        for (int oo=0;oo<4;++oo){
            int o = oo*16+to;
            sOut[pr*68+o] = (v[oo]-m)*rs*sB[320+o]+sB[384+o];
        }
    }
    __syncthreads();
    for (int idx=tid; idx<1024; idx+=256){
        int p = idx>>4, c4 = idx&15;
        *(float4*)(out_adj + ((size_t)bi*384 + j0+p)*64 + c4*4) = *(const float4*)(sOut + p*68 + c4*4);
    }
}

extern "C" void kernel_launch(void* const* d_in, const int* in_sizes, int n_in,
                              void* d_out, int out_size){
    const float* x       = (const float*)d_in[0];
    const float* adj     = (const float*)d_in[1];
    const float* wnq     = (const float*)d_in[2];
    const float* wnk     = (const float*)d_in[3];
    const float* wnv     = (const float*)d_in[4];
    const float* weq     = (const float*)d_in[5];
    const float* wek     = (const float*)d_in[6];
    const float* wev     = (const float*)d_in[7];
    const float* nfc1_w  = (const float*)d_in[8];
    const float* nfc1_b  = (const float*)d_in[9];
    const float* ln1_g   = (const float*)d_in[10];
    const float* ln1_b   = (const float*)d_in[11];
    const float* nfc2_w  = (const float*)d_in[12];
    const float* nfc2_b  = (const float*)d_in[13];
    const float* nfc3_w  = (const float*)d_in[14];
    const float* nfc3_b  = (const float*)d_in[15];
    const float* ln2_g   = (const float*)d_in[16];
    const float* ln2_b   = (const float*)d_in[17];
    const float* efc1_w  = (const float*)d_in[18];
    const float* efc1_b  = (const float*)d_in[19];
    const float* efc2_w  = (const float*)d_in[20];
    const float* efc2_b  = (const float*)d_in[21];
    const float* eln1_g  = (const float*)d_in[22];
    const float* eln1_b  = (const float*)d_in[23];
    const float* efc3_w  = (const float*)d_in[24];
    const float* efc3_b  = (const float*)d_in[25];
    const float* efc4_w  = (const float*)d_in[26];
    const float* efc4_b  = (const float*)d_in[27];
    const float* eln2_g  = (const float*)d_in[28];
    const float* eln2_b  = (const float*)d_in[29];
    float* out_x   = (float*)d_out;
    float* out_adj = out_x + 2*384*128;

    cudaFuncSetAttribute(k_qkv,  cudaFuncAttributeMaxDynamicSharedMemorySize, QKV_SMEM);
    cudaFuncSetAttribute(k_attn, cudaFuncAttributeMaxDynamicSharedMemorySize, ATTN_SMEM);
    cudaFuncSetAttribute(k_node, cudaFuncAttributeMaxDynamicSharedMemorySize, NODE_SMEM);
    cudaFuncSetAttribute(k_edge, cudaFuncAttributeMaxDynamicSharedMemorySize, EDGE_SMEM);

    k_qkv<<<96,256,QKV_SMEM>>>(x, wnq, wnk, wnv);
    k_attn<<<768,256,ATTN_SMEM>>>(adj, weq, wek, wev);
    k_node<<<96,256,NODE_SMEM>>>(x, nfc1_w, nfc1_b, ln1_g, ln1_b, nfc2_w, nfc2_b,
                                 nfc3_w, nfc3_b, ln2_g, ln2_b, efc1_w, out_x);
    k_edge<<<4608,256,EDGE_SMEM>>>(adj, efc1_w, efc1_b, efc2_w, efc2_b,
                                   eln1_g, eln1_b, efc3_w, efc3_b,
                                   efc4_w, efc4_b, eln2_g, eln2_b, out_adj);
}